// round 11
// baseline (speedup 1.0000x reference)
#include <cuda_runtime.h>
#include <cuda_bf16.h>
#include <math.h>

#define B_ 2
#define S_ 4096
#define E_ 1024
#define D_ 64
#define WIN_ 5
#define DIL_ 2

// Scratch (allocation-free rule: __device__ globals)
__device__ float g_Q[B_ * S_ * D_];
__device__ float g_K[B_ * S_ * D_];
__device__ float g_V[B_ * S_ * D_];
__device__ float g_Vsum[B_ * D_];
// W merged+split, K-CONTIGUOUS: [col n (192)][k2 (512)], u32 = {bf16 k even, k odd}
__device__ unsigned g_Wbhi[192 * (E_ / 2)];
__device__ unsigned g_Wblo[192 * (E_ / 2)];

// ---------------------------------------------------------------------------
// helpers
// ---------------------------------------------------------------------------
__device__ __forceinline__ unsigned pack_bf16(float lo_val, float hi_val) {
    __nv_bfloat162 p;
    p.x = __float2bfloat16(lo_val);
    p.y = __float2bfloat16(hi_val);
    return *(unsigned*)&p;
}
__device__ __forceinline__ float bf_residual(float v) {
    __nv_bfloat16 h = __float2bfloat16(v);
    return v - __bfloat162float(h);
}
__device__ __forceinline__ void mma_bf16(float* c, const unsigned* a, const unsigned* b) {
    asm volatile(
        "mma.sync.aligned.m16n8k16.row.col.f32.bf16.bf16.f32 "
        "{%0,%1,%2,%3}, {%4,%5,%6,%7}, {%8,%9}, {%0,%1,%2,%3};"
        : "+f"(c[0]), "+f"(c[1]), "+f"(c[2]), "+f"(c[3])
        : "r"(a[0]), "r"(a[1]), "r"(a[2]), "r"(a[3]), "r"(b[0]), "r"(b[1]));
}
__device__ __forceinline__ void ldsm4(unsigned* r, unsigned addr) {
    asm volatile("ldmatrix.sync.aligned.m8n8.x4.shared.b16 {%0,%1,%2,%3}, [%4];"
                 : "=r"(r[0]), "=r"(r[1]), "=r"(r[2]), "=r"(r[3]) : "r"(addr));
}

// ---------------------------------------------------------------------------
// Kernel 0: W -> merged packed bf16 hi/lo planes, K-contiguous [n][k2].
// Also initializes g_Vsum with the bias contribution: S * bv[d].
// idx order: n-major -> coalesced writes (2 arrays), strided reads (1 array).
// ---------------------------------------------------------------------------
__global__ void wsplit_kernel(const float* __restrict__ Wq,
                              const float* __restrict__ Wk,
                              const float* __restrict__ Wv,
                              const float* __restrict__ bv)
{
    const int idx = blockIdx.x * blockDim.x + threadIdx.x;
    if (blockIdx.x == 0 && threadIdx.x < B_ * D_) {
        g_Vsum[threadIdx.x] = (float)S_ * bv[threadIdx.x & (D_ - 1)];
    }
    if (idx >= 192 * (E_ / 2)) return;
    const int n_col = idx >> 9;           // / 512  -> 0..191
    const int k2 = idx & 511;
    const int mat = n_col >> 6;
    const int nn = n_col & 63;
    const float* src = (mat == 0) ? Wq : (mat == 1) ? Wk : Wv;
    const float v0 = src[(2 * k2) * D_ + nn];
    const float v1 = src[(2 * k2 + 1) * D_ + nn];
    g_Wbhi[idx] = pack_bf16(v0, v1);
    g_Wblo[idx] = pack_bf16(bf_residual(v0), bf_residual(v1));
}

// ---------------------------------------------------------------------------
// Kernel 1: MERGED QKV GEMM, 3xBF16 (hh+lh+hl), m16n8k16 + ldmatrix.x4.
// C[8192 x 192] = x @ [Wq|Wk|Wv] + bias. BM=64, BK=32, 512 thr = 16 warps
// (4m x 4n), warp tile 16x48. Fragments via ldmatrix (16 per warp per tile
// instead of 64 scalar LDS). V-column sums fused in epilogue.
// SMEM layout per stage (u32): AH[64][20], AL[64][20], BH[192][20], BL[192][20]
// A rows: [m][k2 0..15 +pad], B rows: [n][k2 0..15 +pad]; stride 20 u32 = 80B
// (16B-aligned rows; 8-row ldmatrix phases hit distinct bank groups).
// ---------------------------------------------------------------------------
#define BM 64
#define ST 20                 // row stride in u32 for both A and B tiles
#define OFF_AH 0
#define OFF_AL 1280
#define OFF_BH 2560
#define OFF_BL 6400
#define STAGE_U32 10240
#define SMEM_BYTES (2 * STAGE_U32 * 4)

__global__ __launch_bounds__(512) void qkv_gemm_merged(
    const float* __restrict__ x,
    const float* __restrict__ bq,
    const float* __restrict__ bk,
    const float* __restrict__ bv)
{
    extern __shared__ unsigned sm[];
    const unsigned smb = (unsigned)__cvta_generic_to_shared(sm);

    const int tid  = threadIdx.x;
    const int lane = tid & 31;
    const int wid  = tid >> 5;
    const int wm   = wid >> 2;      // 0..3 -> m0 = wm*16
    const int wn   = wid & 3;       // 0..3 -> n0 = wn*48
    const int rowBase = blockIdx.x * BM;
    const int bb = rowBase >> 12;   // batch of this block

    // A global: 64 rows x 8 float4 slots = 512 -> 1 float4/thread
    const int arow = tid >> 3;          // 0..63
    const int af   = tid & 7;           // 0..7 -> k2 = af*2
    const float* aptr = x + (size_t)(rowBase + arow) * E_ + af * 4;

    float acc[6][4];
#pragma unroll
    for (int nt = 0; nt < 6; nt++)
#pragma unroll
        for (int k = 0; k < 4; k++) acc[nt][k] = 0.f;

    const int r  = lane >> 2;
    const int cc = lane & 3;
    const int m0 = wm * 16;
    const int n0 = wn * 48;

    // ldmatrix per-lane byte offsets (within a plane)
    const unsigned a_off =
        ((unsigned)((m0 + (lane & 15)) * ST + ((lane >> 4) << 2))) * 4u;
    const unsigned b_off =
        ((unsigned)((n0 + ((lane >> 4) << 3) + (lane & 7)) * ST + (((lane >> 3) & 1) << 2))) * 4u;

    float4 pa;
    uint2 pbh[3], pbl[3];

    auto load_tile = [&](int kt) {
        pa = *(const float4*)(aptr + kt * 32);
        // B: 192 n-rows x 8 uint2 (16 u32 of k2) = 1536 uint2; 512 thr x 3
#pragma unroll
        for (int i = 0; i < 3; i++) {
            const int e = tid + 512 * i;
            const int n = e >> 3;
            const int j = e & 7;
            const size_t g = (size_t)n * (E_ / 2) + kt * 16 + j * 2;
            pbh[i] = *(const uint2*)(g_Wbhi + g);
            pbl[i] = *(const uint2*)(g_Wblo + g);
        }
    };

    auto store_tile = [&](int st) {
        unsigned* base = sm + st * STAGE_U32;
        uint2 h, l;
        h.x = pack_bf16(pa.x, pa.y);
        h.y = pack_bf16(pa.z, pa.w);
        l.x = pack_bf16(bf_residual(pa.x), bf_residual(pa.y));
        l.y = pack_bf16(bf_residual(pa.z), bf_residual(pa.w));
        *(uint2*)&base[OFF_AH + arow * ST + af * 2] = h;
        *(uint2*)&base[OFF_AL + arow * ST + af * 2] = l;
#pragma unroll
        for (int i = 0; i < 3; i++) {
            const int e = tid + 512 * i;
            const int n = e >> 3;
            const int j = e & 7;
            *(uint2*)&base[OFF_BH + n * ST + j * 2] = pbh[i];
            *(uint2*)&base[OFF_BL + n * ST + j * 2] = pbl[i];
        }
    };

    auto compute_tile = [&](int st) {
        const unsigned sb = smb + (unsigned)(st * STAGE_U32) * 4u;
#pragma unroll
        for (int ks = 0; ks < 2; ks++) {
            const unsigned ko = (unsigned)(ks * 8) * 4u;   // 8 u32 = 32B
            unsigned ah[4], al[4];
            ldsm4(ah, sb + OFF_AH * 4u + a_off + ko);
            ldsm4(al, sb + OFF_AL * 4u + a_off + ko);
            unsigned bh[3][4], bl[3][4];
#pragma unroll
            for (int g = 0; g < 3; g++) {
                const unsigned go = (unsigned)(g * 16 * ST) * 4u;
                ldsm4(bh[g], sb + OFF_BH * 4u + b_off + go + ko);
                ldsm4(bl[g], sb + OFF_BL * 4u + b_off + go + ko);
            }
            // hh, then lh, then hl (dep distance 6)
#pragma unroll
            for (int g = 0; g < 3; g++) {
                mma_bf16(acc[2 * g],     ah, &bh[g][0]);
                mma_bf16(acc[2 * g + 1], ah, &bh[g][2]);
            }
#pragma unroll
            for (int g = 0; g < 3; g++) {
                mma_bf16(acc[2 * g],     al, &bh[g][0]);
                mma_bf16(acc[2 * g + 1], al, &bh[g][2]);
            }
#pragma unroll
            for (int g = 0; g < 3; g++) {
                mma_bf16(acc[2 * g],     ah, &bl[g][0]);
                mma_bf16(acc[2 * g + 1], ah, &bl[g][2]);
            }
        }
    };

    load_tile(0);
    store_tile(0);
    __syncthreads();

    const int KTILES = E_ / 32;   // 32
    for (int kt = 1; kt < KTILES; kt++) {
        load_tile(kt);
        compute_tile((kt - 1) & 1);
        store_tile(kt & 1);            // other buffer: fenced by previous sync
        __syncthreads();
    }
    compute_tile((KTILES - 1) & 1);

    // epilogue: route 8-col groups to Q/K/V with bias; fuse V column sums
#pragma unroll
    for (int nt = 0; nt < 6; nt++) {
        const int colbase = n0 + nt * 8;
        const int mat = colbase >> 6;
        const int ocolb = colbase & 63;
        float* op = (mat == 0) ? g_Q : (mat == 1) ? g_K : g_V;
        const float* bp = (mat == 0) ? bq : (mat == 1) ? bk : bv;
        const int ocol = ocolb + 2 * cc;
        const float b0v = bp[ocol];
        const float b1v = bp[ocol + 1];
        const int row0 = rowBase + m0 + r;
        float2 v0 = make_float2(acc[nt][0] + b0v, acc[nt][1] + b1v);
        float2 v1 = make_float2(acc[nt][2] + b0v, acc[nt][3] + b1v);
        *(float2*)&op[(size_t)row0 * D_ + ocol] = v0;
        *(float2*)&op[(size_t)(row0 + 8) * D_ + ocol] = v1;

        if (mat == 2) {
            float s0 = acc[nt][0] + acc[nt][2];
            float s1 = acc[nt][1] + acc[nt][3];
#pragma unroll
            for (int o = 4; o < 32; o <<= 1) {
                s0 += __shfl_xor_sync(0xffffffffu, s0, o);
                s1 += __shfl_xor_sync(0xffffffffu, s1, o);
            }
            if (r == 0) {
                atomicAdd(&g_Vsum[bb * D_ + ocol], s0);
                atomicAdd(&g_Vsum[bb * D_ + ocol + 1], s1);
            }
        }
    }
}

// ---------------------------------------------------------------------------
// Kernel 2: windowed attention combine. One warp per (b, i).
// out[i] = [ e0*Vsum + sum_w (e_w - e0)*V[j_w] ] / [ sum_w e_w + e0*(S - n_valid) ]
// ---------------------------------------------------------------------------
__global__ __launch_bounds__(256) void attn_kernel(float* __restrict__ out)
{
    const int gw = (blockIdx.x * blockDim.x + threadIdx.x) >> 5;
    const int lane = threadIdx.x & 31;
    if (gw >= B_ * S_) return;

    const int b = gw >> 12;
    const int i = gw & (S_ - 1);

    const float* Qr = g_Q + (size_t)gw * D_;
    const float q0 = Qr[lane];
    const float q1 = Qr[lane + 32];

    float c[WIN_];
    bool valid[WIN_];
    int jv[WIN_];
    int nv = 0;
    float cmax = 0.f;

#pragma unroll
    for (int w = 0; w < WIN_; w++) {
        const int j = i + DIL_ * (w - WIN_ / 2);
        jv[w] = j;
        valid[w] = (j >= 0) && (j < S_);
        float p = 0.f;
        if (valid[w]) {
            const float* Kr = g_K + ((size_t)b * S_ + j) * D_;
            p = q0 * Kr[lane] + q1 * Kr[lane + 32];
#pragma unroll
            for (int o = 16; o > 0; o >>= 1)
                p += __shfl_xor_sync(0xffffffffu, p, o);
            nv++;
            cmax = fmaxf(cmax, p);
        }
        c[w] = p;
    }

    const float vs0 = g_Vsum[b * D_ + lane];
    const float vs1 = g_Vsum[b * D_ + lane + 32];

    const float e0 = expf(-cmax);
    float denom = e0 * (float)(S_ - nv);
    float acc0 = e0 * vs0;
    float acc1 = e0 * vs1;

#pragma unroll
    for (int w = 0; w < WIN_; w++) {
        if (valid[w]) {
            const float ew = expf(c[w] - cmax);
            denom += ew;
            const float f = ew - e0;
            const float* Vr = g_V + ((size_t)b * S_ + jv[w]) * D_;
            acc0 = fmaf(f, Vr[lane], acc0);
            acc1 = fmaf(f, Vr[lane + 32], acc1);
        }
    }

    const float inv = 1.f / denom;
    out[(size_t)gw * D_ + lane] = acc0 * inv;
    out[(size_t)gw * D_ + lane + 32] = acc1 * inv;
}

// ---------------------------------------------------------------------------
extern "C" void kernel_launch(void* const* d_in, const int* in_sizes, int n_in,
                              void* d_out, int out_size)
{
    const float* x  = (const float*)d_in[0];
    const float* Wq = (const float*)d_in[1];
    const float* bq = (const float*)d_in[2];
    const float* Wk = (const float*)d_in[3];
    const float* bk = (const float*)d_in[4];
    const float* Wv = (const float*)d_in[5];
    const float* bv = (const float*)d_in[6];
    float* out = (float*)d_out;

    static int configured = 0;
    if (!configured) {
        cudaFuncSetAttribute(qkv_gemm_merged,
                             cudaFuncAttributeMaxDynamicSharedMemorySize,
                             SMEM_BYTES);
        configured = 1;
    }

    wsplit_kernel<<<(192 * (E_ / 2) + 255) / 256, 256>>>(Wq, Wk, Wv, bv);

    qkv_gemm_merged<<<(B_ * S_) / BM, 512, SMEM_BYTES>>>(x, bq, bk, bv);

    const int warps = B_ * S_;
    attn_kernel<<<(warps * 32 + 255) / 256, 256>>>(out);
}

// round 12
// speedup vs baseline: 1.0043x; 1.0043x over previous
#include <cuda_runtime.h>
#include <cuda_bf16.h>
#include <math.h>

#define B_ 2
#define S_ 4096
#define E_ 1024
#define D_ 64
#define WIN_ 5
#define DIL_ 2

// Scratch (allocation-free rule: __device__ globals)
__device__ float g_Q[B_ * S_ * D_];
__device__ float g_K[B_ * S_ * D_];
__device__ float g_V[B_ * S_ * D_];
__device__ float g_Vsum[B_ * D_];
// W merged+split: [k2][col], col = mat*64 + n, u32 = packed bf16 {2k2, 2k2+1}
__device__ unsigned g_Wbhi[(E_ / 2) * 192];
__device__ unsigned g_Wblo[(E_ / 2) * 192];

// ---------------------------------------------------------------------------
// bf16 helpers
// ---------------------------------------------------------------------------
__device__ __forceinline__ unsigned pack_bf16(float lo_val, float hi_val) {
    __nv_bfloat162 p;
    p.x = __float2bfloat16(lo_val);
    p.y = __float2bfloat16(hi_val);
    return *(unsigned*)&p;
}
__device__ __forceinline__ float bf_residual(float v) {
    __nv_bfloat16 h = __float2bfloat16(v);
    return v - __bfloat162float(h);
}
__device__ __forceinline__ void mma_bf16(float* c, const unsigned* a, const unsigned* b) {
    asm volatile(
        "mma.sync.aligned.m16n8k16.row.col.f32.bf16.bf16.f32 "
        "{%0,%1,%2,%3}, {%4,%5,%6,%7}, {%8,%9}, {%0,%1,%2,%3};"
        : "+f"(c[0]), "+f"(c[1]), "+f"(c[2]), "+f"(c[3])
        : "r"(a[0]), "r"(a[1]), "r"(a[2]), "r"(a[3]), "r"(b[0]), "r"(b[1]));
}

// ---------------------------------------------------------------------------
// Kernel 0: W -> merged packed bf16 hi/lo planes, [k2][col]. Vectorized:
// each thread converts 4 columns of one k2-row (2 float4 reads, 2 uint4
// writes). Also initializes g_Vsum with the bias contribution S * bv[d].
// ---------------------------------------------------------------------------
__global__ void wsplit_kernel(const float* __restrict__ Wq,
                              const float* __restrict__ Wk,
                              const float* __restrict__ Wv,
                              const float* __restrict__ bv)
{
    const int idx = blockIdx.x * blockDim.x + threadIdx.x;
    if (blockIdx.x == 0 && threadIdx.x < B_ * D_) {
        g_Vsum[threadIdx.x] = (float)S_ * bv[threadIdx.x & (D_ - 1)];
    }
    if (idx >= (E_ / 2) * 48) return;
    const int k2 = idx / 48;
    const int c4 = (idx - k2 * 48) * 4;     // column group (4), mat-aligned
    const int mat = c4 >> 6;
    const int n = c4 & 63;
    const float* src = (mat == 0) ? Wq : (mat == 1) ? Wk : Wv;
    const float4 r0 = *(const float4*)&src[(size_t)(2 * k2) * D_ + n];
    const float4 r1 = *(const float4*)&src[(size_t)(2 * k2 + 1) * D_ + n];
    uint4 h, l;
    h.x = pack_bf16(r0.x, r1.x); l.x = pack_bf16(bf_residual(r0.x), bf_residual(r1.x));
    h.y = pack_bf16(r0.y, r1.y); l.y = pack_bf16(bf_residual(r0.y), bf_residual(r1.y));
    h.z = pack_bf16(r0.z, r1.z); l.z = pack_bf16(bf_residual(r0.z), bf_residual(r1.z));
    h.w = pack_bf16(r0.w, r1.w); l.w = pack_bf16(bf_residual(r0.w), bf_residual(r1.w));
    *(uint4*)&g_Wbhi[k2 * 192 + c4] = h;
    *(uint4*)&g_Wblo[k2 * 192 + c4] = l;
}

// ---------------------------------------------------------------------------
// Kernel 1: MERGED QKV GEMM, 3xBF16 (hh+lh+hl) on m16n8k16, BK=32.
// C[8192 x 192] = x @ [Wq|Wk|Wv] + bias. BM=64, 256 thr = 8 warps (2m x 4n),
// warp tile 32x48. V-column sums fused in epilogue. (R9 configuration.)
// ---------------------------------------------------------------------------
#define BM 64
#define SA 20     // As row stride (u32)
#define SB 200    // Bs row stride (u32)

#define OFF_AH(s) ((s) * 1280)
#define OFF_AL(s) (2560 + (s) * 1280)
#define OFF_BH(s) (5120 + (s) * 3200)
#define OFF_BL(s) (11520 + (s) * 3200)
#define SMEM_U32  17920

__global__ __launch_bounds__(256) void qkv_gemm_merged(
    const float* __restrict__ x,
    const float* __restrict__ bq,
    const float* __restrict__ bk,
    const float* __restrict__ bv)
{
    extern __shared__ unsigned sm[];

    const int tid  = threadIdx.x;
    const int lane = tid & 31;
    const int wid  = tid >> 5;
    const int wm   = wid >> 2;      // 0..1 -> m0 = wm*32
    const int wn   = wid & 3;       // 0..3 -> n0 = wn*48
    const int rowBase = blockIdx.x * BM;
    const int bb = rowBase >> 12;

    const int arow = tid >> 2;          // 0..63
    const int af   = tid & 3;           // 0..3
    const float* aptr = x + (size_t)(rowBase + arow) * E_ + af * 8;

    float acc[2][6][4];
#pragma unroll
    for (int mt = 0; mt < 2; mt++)
#pragma unroll
        for (int nt = 0; nt < 6; nt++)
#pragma unroll
            for (int k = 0; k < 4; k++) acc[mt][nt][k] = 0.f;

    const int r  = lane >> 2;
    const int cc = lane & 3;
    const int m0 = wm * 32;
    const int n0 = wn * 48;

    float4 pa0, pa1;
    uint2 pbh[6], pbl[6];

    auto load_tile = [&](int kt) {
        pa0 = *(const float4*)(aptr + kt * 32);
        pa1 = *(const float4*)(aptr + kt * 32 + 4);
        const unsigned* wh = g_Wbhi + (size_t)kt * 16 * 192;
        const unsigned* wl = g_Wblo + (size_t)kt * 16 * 192;
#pragma unroll
        for (int i = 0; i < 6; i++) {
            const int e = tid + 256 * i;
            pbh[i] = *(const uint2*)(wh + e * 2);
            pbl[i] = *(const uint2*)(wl + e * 2);
        }
    };

    auto store_tile = [&](int st) {
        uint4 h, l;
        h.x = pack_bf16(pa0.x, pa0.y);
        h.y = pack_bf16(pa0.z, pa0.w);
        h.z = pack_bf16(pa1.x, pa1.y);
        h.w = pack_bf16(pa1.z, pa1.w);
        l.x = pack_bf16(bf_residual(pa0.x), bf_residual(pa0.y));
        l.y = pack_bf16(bf_residual(pa0.z), bf_residual(pa0.w));
        l.z = pack_bf16(bf_residual(pa1.x), bf_residual(pa1.y));
        l.w = pack_bf16(bf_residual(pa1.z), bf_residual(pa1.w));
        *(uint4*)&sm[OFF_AH(st) + arow * SA + af * 4] = h;
        *(uint4*)&sm[OFF_AL(st) + arow * SA + af * 4] = l;
#pragma unroll
        for (int i = 0; i < 6; i++) {
            const int e = tid + 256 * i;
            const int krow = e / 96;
            const int cu2 = e - krow * 96;
            *(uint2*)&sm[OFF_BH(st) + krow * SB + cu2 * 2] = pbh[i];
            *(uint2*)&sm[OFF_BL(st) + krow * SB + cu2 * 2] = pbl[i];
        }
    };

    auto compute_tile = [&](int st) {
        const unsigned* AH = sm + OFF_AH(st);
        const unsigned* AL = sm + OFF_AL(st);
        const unsigned* BH = sm + OFF_BH(st);
        const unsigned* BL = sm + OFF_BL(st);
#pragma unroll
        for (int ks = 0; ks < 2; ks++) {
            const int kc = ks * 8 + cc;
            unsigned ah[2][4], al[2][4];
#pragma unroll
            for (int mt = 0; mt < 2; mt++) {
                const int mr = m0 + mt * 16 + r;
                ah[mt][0] = AH[mr * SA + kc];
                ah[mt][1] = AH[(mr + 8) * SA + kc];
                ah[mt][2] = AH[mr * SA + kc + 4];
                ah[mt][3] = AH[(mr + 8) * SA + kc + 4];
                al[mt][0] = AL[mr * SA + kc];
                al[mt][1] = AL[(mr + 8) * SA + kc];
                al[mt][2] = AL[mr * SA + kc + 4];
                al[mt][3] = AL[(mr + 8) * SA + kc + 4];
            }
            unsigned bh[6][2], bl[6][2];
#pragma unroll
            for (int nt = 0; nt < 6; nt++) {
                const int n = n0 + nt * 8 + r;
                bh[nt][0] = BH[kc * SB + n];
                bh[nt][1] = BH[(kc + 4) * SB + n];
                bl[nt][0] = BL[kc * SB + n];
                bl[nt][1] = BL[(kc + 4) * SB + n];
            }
#pragma unroll
            for (int mt = 0; mt < 2; mt++)
#pragma unroll
                for (int nt = 0; nt < 6; nt++) mma_bf16(acc[mt][nt], ah[mt], bh[nt]);
#pragma unroll
            for (int mt = 0; mt < 2; mt++)
#pragma unroll
                for (int nt = 0; nt < 6; nt++) mma_bf16(acc[mt][nt], al[mt], bh[nt]);
#pragma unroll
            for (int mt = 0; mt < 2; mt++)
#pragma unroll
                for (int nt = 0; nt < 6; nt++) mma_bf16(acc[mt][nt], ah[mt], bl[nt]);
        }
    };

    load_tile(0);
    store_tile(0);
    __syncthreads();

    const int KTILES = E_ / 32;   // 32
    for (int kt = 1; kt < KTILES; kt++) {
        load_tile(kt);
        compute_tile((kt - 1) & 1);
        store_tile(kt & 1);
        __syncthreads();
    }
    compute_tile((KTILES - 1) & 1);

#pragma unroll
    for (int nt = 0; nt < 6; nt++) {
        const int colbase = n0 + nt * 8;
        const int mat = colbase >> 6;
        const int ocolb = colbase & 63;
        float* op = (mat == 0) ? g_Q : (mat == 1) ? g_K : g_V;
        const float* bp = (mat == 0) ? bq : (mat == 1) ? bk : bv;
        const int ocol = ocolb + 2 * cc;
        const float b0v = bp[ocol];
        const float b1v = bp[ocol + 1];
#pragma unroll
        for (int mt = 0; mt < 2; mt++) {
            const int row0 = rowBase + m0 + mt * 16 + r;
            float2 v0 = make_float2(acc[mt][nt][0] + b0v, acc[mt][nt][1] + b1v);
            float2 v1 = make_float2(acc[mt][nt][2] + b0v, acc[mt][nt][3] + b1v);
            *(float2*)&op[(size_t)row0 * D_ + ocol] = v0;
            *(float2*)&op[(size_t)(row0 + 8) * D_ + ocol] = v1;
        }
        if (mat == 2) {
            float s0 = acc[0][nt][0] + acc[0][nt][2] + acc[1][nt][0] + acc[1][nt][2];
            float s1 = acc[0][nt][1] + acc[0][nt][3] + acc[1][nt][1] + acc[1][nt][3];
#pragma unroll
            for (int o = 4; o < 32; o <<= 1) {
                s0 += __shfl_xor_sync(0xffffffffu, s0, o);
                s1 += __shfl_xor_sync(0xffffffffu, s1, o);
            }
            if (r == 0) {
                atomicAdd(&g_Vsum[bb * D_ + ocol], s0);
                atomicAdd(&g_Vsum[bb * D_ + ocol + 1], s1);
            }
        }
    }
}

// ---------------------------------------------------------------------------
// Kernel 2: windowed attention, smem-tiled. One block per 64 positions:
// stage Q[64], K/V halo [72 rows] in smem; warp w handles 8 positions.
// out[i] = [ e0*Vsum + sum_w (e_w - e0)*V[j_w] ] / [ sum_w e_w + e0*(S - nv) ]
// smem: sQ 16KB + sK 18KB + sV 18KB = 52KB dynamic.
// ---------------------------------------------------------------------------
#define ATTN_SMEM ((64 * 64 + 2 * 72 * 64) * 4)

__global__ __launch_bounds__(256) void attn_kernel(float* __restrict__ out)
{
    extern __shared__ float s[];
    float* sQ = s;                  // [64][64]
    float* sK = s + 64 * 64;        // [72][64]
    float* sV = sK + 72 * 64;       // [72][64]

    const int tid = threadIdx.x;
    const int b = blockIdx.x >> 6;          // 64 blocks per batch
    const int c = (blockIdx.x & 63) * 64;   // chunk base position

    const float* Qb = g_Q + (size_t)b * S_ * D_;
    const float* Kb = g_K + (size_t)b * S_ * D_;
    const float* Vb = g_V + (size_t)b * S_ * D_;

    // stage Q rows [c, c+64)
    for (int e = tid; e < 64 * 16; e += 256) {
        const int row = e >> 4, f = e & 15;
        *(float4*)&sQ[row * 64 + f * 4] =
            *(const float4*)&Qb[(size_t)(c + row) * D_ + f * 4];
    }
    // stage K/V halo rows [c-4, c+68)
    for (int e = tid; e < 72 * 16; e += 256) {
        const int row = e >> 4, f = e & 15;
        const int j = c - 4 + row;
        if (j >= 0 && j < S_) {
            *(float4*)&sK[row * 64 + f * 4] = *(const float4*)&Kb[(size_t)j * D_ + f * 4];
            *(float4*)&sV[row * 64 + f * 4] = *(const float4*)&Vb[(size_t)j * D_ + f * 4];
        }
    }
    __syncthreads();

    const int lane = tid & 31;
    const int w = tid >> 5;
    const float vs0 = g_Vsum[b * D_ + lane];
    const float vs1 = g_Vsum[b * D_ + lane + 32];

#pragma unroll
    for (int p = 0; p < 8; p++) {
        const int li = w * 8 + p;       // local position 0..63
        const int i = c + li;
        const float q0 = sQ[li * 64 + lane];
        const float q1 = sQ[li * 64 + lane + 32];

        float cs[WIN_];
        bool valid[WIN_];
        int nv = 0;
        float cmax = 0.f;   // softmax row includes zeros -> max includes 0
#pragma unroll
        for (int t = 0; t < WIN_; t++) {
            const int j = i + DIL_ * (t - WIN_ / 2);
            valid[t] = (j >= 0) && (j < S_);
            float pp = 0.f;
            if (valid[t]) {
                const float* Kr = &sK[(li + 2 * t) * 64];   // row = li+4+2(t-2)
                pp = q0 * Kr[lane] + q1 * Kr[lane + 32];
#pragma unroll
                for (int o = 16; o > 0; o >>= 1)
                    pp += __shfl_xor_sync(0xffffffffu, pp, o);
                nv++;
                cmax = fmaxf(cmax, pp);
            }
            cs[t] = pp;
        }

        const float e0 = expf(-cmax);
        float denom = e0 * (float)(S_ - nv);
        float a0 = e0 * vs0;
        float a1 = e0 * vs1;
#pragma unroll
        for (int t = 0; t < WIN_; t++) {
            if (valid[t]) {
                const float ew = expf(cs[t] - cmax);
                denom += ew;
                const float f = ew - e0;
                const float* Vr = &sV[(li + 2 * t) * 64];
                a0 = fmaf(f, Vr[lane], a0);
                a1 = fmaf(f, Vr[lane + 32], a1);
            }
        }
        const float inv = 1.f / denom;
        float* op = out + (size_t)(b * S_ + i) * D_;
        op[lane] = a0 * inv;
        op[lane + 32] = a1 * inv;
    }
}

// ---------------------------------------------------------------------------
extern "C" void kernel_launch(void* const* d_in, const int* in_sizes, int n_in,
                              void* d_out, int out_size)
{
    const float* x  = (const float*)d_in[0];
    const float* Wq = (const float*)d_in[1];
    const float* bq = (const float*)d_in[2];
    const float* Wk = (const float*)d_in[3];
    const float* bk = (const float*)d_in[4];
    const float* Wv = (const float*)d_in[5];
    const float* bv = (const float*)d_in[6];
    float* out = (float*)d_out;

    static int configured = 0;
    if (!configured) {
        cudaFuncSetAttribute(qkv_gemm_merged,
                             cudaFuncAttributeMaxDynamicSharedMemorySize,
                             SMEM_U32 * 4);
        cudaFuncSetAttribute(attn_kernel,
                             cudaFuncAttributeMaxDynamicSharedMemorySize,
                             ATTN_SMEM);
        configured = 1;
    }

    wsplit_kernel<<<((E_ / 2) * 48 + 255) / 256, 256>>>(Wq, Wk, Wv, bv);

    qkv_gemm_merged<<<(B_ * S_) / BM, 256, SMEM_U32 * 4>>>(x, bq, bk, bv);

    attn_kernel<<<(B_ * S_) / 64, 256, ATTN_SMEM>>>(out);
}

// round 14
// speedup vs baseline: 1.3138x; 1.3082x over previous
#include <cuda_runtime.h>
#include <cuda_bf16.h>
#include <math.h>

#define B_ 2
#define S_ 4096
#define E_ 1024
#define D_ 64
#define WIN_ 5
#define DIL_ 2

// Scratch (allocation-free rule: __device__ globals)
__device__ float g_Q[B_ * S_ * D_];
__device__ float g_K[B_ * S_ * D_];
__device__ float g_V[B_ * S_ * D_];
__device__ float g_Vsum[B_ * D_];
// W merged+split: [k2][col], col = mat*64 + n, u32 = packed bf16 {2k2, 2k2+1}
__device__ unsigned g_Wbhi[(E_ / 2) * 192];
__device__ unsigned g_Wblo[(E_ / 2) * 192];

// ---------------------------------------------------------------------------
// helpers
// ---------------------------------------------------------------------------
__device__ __forceinline__ unsigned pack_bf16(float lo_val, float hi_val) {
    __nv_bfloat162 p;
    p.x = __float2bfloat16(lo_val);
    p.y = __float2bfloat16(hi_val);
    return *(unsigned*)&p;
}
__device__ __forceinline__ float bf_residual(float v) {
    __nv_bfloat16 h = __float2bfloat16(v);
    return v - __bfloat162float(h);
}
__device__ __forceinline__ void mma_bf16(float* c, const unsigned* a, const unsigned* b) {
    asm volatile(
        "mma.sync.aligned.m16n8k16.row.col.f32.bf16.bf16.f32 "
        "{%0,%1,%2,%3}, {%4,%5,%6,%7}, {%8,%9}, {%0,%1,%2,%3};"
        : "+f"(c[0]), "+f"(c[1]), "+f"(c[2]), "+f"(c[3])
        : "r"(a[0]), "r"(a[1]), "r"(a[2]), "r"(a[3]), "r"(b[0]), "r"(b[1]));
}
__device__ __forceinline__ void cp_async16(unsigned smem_addr, const void* gptr) {
    asm volatile("cp.async.cg.shared.global [%0], [%1], 16;"
                 :: "r"(smem_addr), "l"(gptr) : "memory");
}
__device__ __forceinline__ void cp_commit() {
    asm volatile("cp.async.commit_group;" ::: "memory");
}
__device__ __forceinline__ void cp_wait0() {
    asm volatile("cp.async.wait_group 0;" ::: "memory");
}

// ---------------------------------------------------------------------------
// Kernel 0: W -> merged packed bf16 hi/lo planes, [k2][col]. Vectorized.
// Also initializes g_Vsum with the bias contribution S * bv[d].
// ---------------------------------------------------------------------------
__global__ void wsplit_kernel(const float* __restrict__ Wq,
                              const float* __restrict__ Wk,
                              const float* __restrict__ Wv,
                              const float* __restrict__ bv)
{
    const int idx = blockIdx.x * blockDim.x + threadIdx.x;
    if (blockIdx.x == 0 && threadIdx.x < B_ * D_) {
        g_Vsum[threadIdx.x] = (float)S_ * bv[threadIdx.x & (D_ - 1)];
    }
    if (idx >= (E_ / 2) * 48) return;
    const int k2 = idx / 48;
    const int c4 = (idx - k2 * 48) * 4;     // column group (4), mat-aligned
    const int mat = c4 >> 6;
    const int n = c4 & 63;
    const float* src = (mat == 0) ? Wq : (mat == 1) ? Wk : Wv;
    const float4 r0 = *(const float4*)&src[(size_t)(2 * k2) * D_ + n];
    const float4 r1 = *(const float4*)&src[(size_t)(2 * k2 + 1) * D_ + n];
    uint4 h, l;
    h.x = pack_bf16(r0.x, r1.x); l.x = pack_bf16(bf_residual(r0.x), bf_residual(r1.x));
    h.y = pack_bf16(r0.y, r1.y); l.y = pack_bf16(bf_residual(r0.y), bf_residual(r1.y));
    h.z = pack_bf16(r0.z, r1.z); l.z = pack_bf16(bf_residual(r0.z), bf_residual(r1.z));
    h.w = pack_bf16(r0.w, r1.w); l.w = pack_bf16(bf_residual(r0.w), bf_residual(r1.w));
    *(uint4*)&g_Wbhi[k2 * 192 + c4] = h;
    *(uint4*)&g_Wblo[k2 * 192 + c4] = l;
}

// ---------------------------------------------------------------------------
// Kernel 1: MERGED QKV GEMM, 3xBF16 (hh+lh+hl) on m16n8k16, BK=32.
// C[8192 x 192] = x @ [Wq|Wk|Wv] + bias. BM=64, 256 thr = 8 warps (2m x 4n),
// warp tile 32x48. B planes staged via cp.async.cg: 6 x 16B per thread per
// tile (1536 chunks: hi 0..767, lo 768..1535), replacing 24 LDG/STS instrs.
// A staged through registers (fp32->bf16 hi/lo split at STS). Ping-pong.
// ---------------------------------------------------------------------------
#define BM 64
#define SA 20     // As row stride (u32)
#define SB 200    // Bs row stride (u32); 800B rows, 16B-aligned

// u32 offsets within dynamic smem; stage stride 8960 u32 (35840B)
#define OFF_AH(s) ((s) * 8960)
#define OFF_AL(s) ((s) * 8960 + 1280)
#define OFF_BH(s) ((s) * 8960 + 2560)
#define OFF_BL(s) ((s) * 8960 + 5760)
#define SMEM_U32  17920

__global__ __launch_bounds__(256) void qkv_gemm_merged(
    const float* __restrict__ x,
    const float* __restrict__ bq,
    const float* __restrict__ bk,
    const float* __restrict__ bv)
{
    extern __shared__ unsigned sm[];
    const unsigned smb = (unsigned)__cvta_generic_to_shared(sm);

    const int tid  = threadIdx.x;
    const int lane = tid & 31;
    const int wid  = tid >> 5;
    const int wm   = wid >> 2;      // 0..1 -> m0 = wm*32
    const int wn   = wid & 3;       // 0..3 -> n0 = wn*48
    const int rowBase = blockIdx.x * BM;
    const int bb = rowBase >> 12;

    const int arow = tid >> 2;          // 0..63
    const int af   = tid & 3;           // 0..3
    const float* aptr = x + (size_t)(rowBase + arow) * E_ + af * 8;

    float acc[2][6][4];
#pragma unroll
    for (int mt = 0; mt < 2; mt++)
#pragma unroll
        for (int nt = 0; nt < 6; nt++)
#pragma unroll
            for (int k = 0; k < 4; k++) acc[mt][nt][k] = 0.f;

    const int r  = lane >> 2;
    const int cc = lane & 3;
    const int m0 = wm * 32;
    const int n0 = wn * 48;

    float4 pa0, pa1;

    auto load_A = [&](int kt) {
        pa0 = *(const float4*)(aptr + kt * 32);
        pa1 = *(const float4*)(aptr + kt * 32 + 4);
    };

    // B: per stage 2 planes x 16 rows x 192 u32 = 1536 16B-chunks.
    // chunk e = tid + 256*i: i<3 -> hi plane, i>=3 -> lo plane.
    // f = e - 768*plane; row = f/48; col = (f%48)*4 u32 (16B step).
    auto issue_B = [&](int kt, int st) {
#pragma unroll
        for (int i = 0; i < 6; i++) {
            const int e = tid + 256 * i;
            const bool lo = (i >= 3);
            const int f = e - (lo ? 768 : 0);
            const int row = f / 48;
            const int c = (f - row * 48) * 4;
            const unsigned* gsrc = (lo ? g_Wblo : g_Wbhi)
                + (size_t)(kt * 16 + row) * 192 + c;
            const unsigned dst = smb +
                ((lo ? OFF_BL(st) : OFF_BH(st)) + row * SB + c) * 4u;
            cp_async16(dst, gsrc);
        }
        cp_commit();
    };

    auto store_A = [&](int st) {
        uint4 h, l;
        h.x = pack_bf16(pa0.x, pa0.y);
        h.y = pack_bf16(pa0.z, pa0.w);
        h.z = pack_bf16(pa1.x, pa1.y);
        h.w = pack_bf16(pa1.z, pa1.w);
        l.x = pack_bf16(bf_residual(pa0.x), bf_residual(pa0.y));
        l.y = pack_bf16(bf_residual(pa0.z), bf_residual(pa0.w));
        l.z = pack_bf16(bf_residual(pa1.x), bf_residual(pa1.y));
        l.w = pack_bf16(bf_residual(pa1.z), bf_residual(pa1.w));
        *(uint4*)&sm[OFF_AH(st) + arow * SA + af * 4] = h;
        *(uint4*)&sm[OFF_AL(st) + arow * SA + af * 4] = l;
    };

    auto compute_tile = [&](int st) {
        const unsigned* AH = sm + OFF_AH(st);
        const unsigned* AL = sm + OFF_AL(st);
        const unsigned* BH = sm + OFF_BH(st);
        const unsigned* BL = sm + OFF_BL(st);
#pragma unroll
        for (int ks = 0; ks < 2; ks++) {
            const int kc = ks * 8 + cc;
            unsigned ah[2][4], al[2][4];
#pragma unroll
            for (int mt = 0; mt < 2; mt++) {
                const int mr = m0 + mt * 16 + r;
                ah[mt][0] = AH[mr * SA + kc];
                ah[mt][1] = AH[(mr + 8) * SA + kc];
                ah[mt][2] = AH[mr * SA + kc + 4];
                ah[mt][3] = AH[(mr + 8) * SA + kc + 4];
                al[mt][0] = AL[mr * SA + kc];
                al[mt][1] = AL[(mr + 8) * SA + kc];
                al[mt][2] = AL[mr * SA + kc + 4];
                al[mt][3] = AL[(mr + 8) * SA + kc + 4];
            }
            unsigned bh[6][2], bl[6][2];
#pragma unroll
            for (int nt = 0; nt < 6; nt++) {
                const int n = n0 + nt * 8 + r;
                bh[nt][0] = BH[kc * SB + n];
                bh[nt][1] = BH[(kc + 4) * SB + n];
                bl[nt][0] = BL[kc * SB + n];
                bl[nt][1] = BL[(kc + 4) * SB + n];
            }
#pragma unroll
            for (int mt = 0; mt < 2; mt++)
#pragma unroll
                for (int nt = 0; nt < 6; nt++) mma_bf16(acc[mt][nt], ah[mt], bh[nt]);
#pragma unroll
            for (int mt = 0; mt < 2; mt++)
#pragma unroll
                for (int nt = 0; nt < 6; nt++) mma_bf16(acc[mt][nt], al[mt], bh[nt]);
#pragma unroll
            for (int mt = 0; mt < 2; mt++)
#pragma unroll
                for (int nt = 0; nt < 6; nt++) mma_bf16(acc[mt][nt], ah[mt], bl[nt]);
        }
    };

    // prologue: tile 0 -> stage 0
    load_A(0);
    issue_B(0, 0);
    store_A(0);
    cp_wait0();
    __syncthreads();

    const int KTILES = E_ / 32;   // 32
    for (int kt = 1; kt < KTILES; kt++) {
        load_A(kt);                    // LDG latency covered by compute
        issue_B(kt, kt & 1);           // async into other stage
        compute_tile((kt - 1) & 1);
        store_A(kt & 1);
        cp_wait0();
        __syncthreads();
    }
    compute_tile((KTILES - 1) & 1);

    // epilogue: route 8-col groups to Q/K/V with bias; fuse V column sums
#pragma unroll
    for (int nt = 0; nt < 6; nt++) {
        const int colbase = n0 + nt * 8;
        const int mat = colbase >> 6;
        const int ocolb = colbase & 63;
        float* op = (mat == 0) ? g_Q : (mat == 1) ? g_K : g_V;
        const float* bp = (mat == 0) ? bq : (mat == 1) ? bk : bv;
        const int ocol = ocolb + 2 * cc;
        const float b0v = bp[ocol];
        const float b1v = bp[ocol + 1];
#pragma unroll
        for (int mt = 0; mt < 2; mt++) {
            const int row0 = rowBase + m0 + mt * 16 + r;
            float2 v0 = make_float2(acc[mt][nt][0] + b0v, acc[mt][nt][1] + b1v);
            float2 v1 = make_float2(acc[mt][nt][2] + b0v, acc[mt][nt][3] + b1v);
            *(float2*)&op[(size_t)row0 * D_ + ocol] = v0;
            *(float2*)&op[(size_t)(row0 + 8) * D_ + ocol] = v1;
        }
        if (mat == 2) {
            float s0 = acc[0][nt][0] + acc[0][nt][2] + acc[1][nt][0] + acc[1][nt][2];
            float s1 = acc[0][nt][1] + acc[0][nt][3] + acc[1][nt][1] + acc[1][nt][3];
#pragma unroll
            for (int o = 4; o < 32; o <<= 1) {
                s0 += __shfl_xor_sync(0xffffffffu, s0, o);
                s1 += __shfl_xor_sync(0xffffffffu, s1, o);
            }
            if (r == 0) {
                atomicAdd(&g_Vsum[bb * D_ + ocol], s0);
                atomicAdd(&g_Vsum[bb * D_ + ocol + 1], s1);
            }
        }
    }
}

// ---------------------------------------------------------------------------
// Kernel 2: windowed attention combine. One warp per (b, i). (R9 version.)
// out[i] = [ e0*Vsum + sum_w (e_w - e0)*V[j_w] ] / [ sum_w e_w + e0*(S - nv) ]
// ---------------------------------------------------------------------------
__global__ __launch_bounds__(256) void attn_kernel(float* __restrict__ out)
{
    const int gw = (blockIdx.x * blockDim.x + threadIdx.x) >> 5;
    const int lane = threadIdx.x & 31;
    if (gw >= B_ * S_) return;

    const int b = gw >> 12;
    const int i = gw & (S_ - 1);

    const float* Qr = g_Q + (size_t)gw * D_;
    const float q0 = Qr[lane];
    const float q1 = Qr[lane + 32];

    float c[WIN_];
    bool valid[WIN_];
    int jv[WIN_];
    int nv = 0;
    float cmax = 0.f;

#pragma unroll
    for (int w = 0; w < WIN_; w++) {
        const int j = i + DIL_ * (w - WIN_ / 2);
        jv[w] = j;
        valid[w] = (j >= 0) && (j < S_);
        float p = 0.f;
        if (valid[w]) {
            const float* Kr = g_K + ((size_t)b * S_ + j) * D_;
            p = q0 * Kr[lane] + q1 * Kr[lane + 32];
#pragma unroll
            for (int o = 16; o > 0; o >>= 1)
                p += __shfl_xor_sync(0xffffffffu, p, o);
            nv++;
            cmax = fmaxf(cmax, p);
        }
        c[w] = p;
    }

    const float vs0 = g_Vsum[b * D_ + lane];
    const float vs1 = g_Vsum[b * D_ + lane + 32];

    const float e0 = expf(-cmax);
    float denom = e0 * (float)(S_ - nv);
    float acc0 = e0 * vs0;
    float acc1 = e0 * vs1;

#pragma unroll
    for (int w = 0; w < WIN_; w++) {
        if (valid[w]) {
            const float ew = expf(c[w] - cmax);
            denom += ew;
            const float f = ew - e0;
            const float* Vr = g_V + ((size_t)b * S_ + jv[w]) * D_;
            acc0 = fmaf(f, Vr[lane], acc0);
            acc1 = fmaf(f, Vr[lane + 32], acc1);
        }
    }

    const float inv = 1.f / denom;
    out[(size_t)gw * D_ + lane] = acc0 * inv;
    out[(size_t)gw * D_ + lane + 32] = acc1 * inv;
}

// ---------------------------------------------------------------------------
extern "C" void kernel_launch(void* const* d_in, const int* in_sizes, int n_in,
                              void* d_out, int out_size)
{
    const float* x  = (const float*)d_in[0];
    const float* Wq = (const float*)d_in[1];
    const float* bq = (const float*)d_in[2];
    const float* Wk = (const float*)d_in[3];
    const float* bk = (const float*)d_in[4];
    const float* Wv = (const float*)d_in[5];
    const float* bv = (const float*)d_in[6];
    float* out = (float*)d_out;

    static int configured = 0;
    if (!configured) {
        cudaFuncSetAttribute(qkv_gemm_merged,
                             cudaFuncAttributeMaxDynamicSharedMemorySize,
                             SMEM_U32 * 4);
        configured = 1;
    }

    wsplit_kernel<<<((E_ / 2) * 48 + 255) / 256, 256>>>(Wq, Wk, Wv, bv);

    qkv_gemm_merged<<<(B_ * S_) / BM, 256, SMEM_U32 * 4>>>(x, bq, bk, bv);

    const int warps = B_ * S_;
    attn_kernel<<<(warps * 32 + 255) / 256, 256>>>(out);
}